// round 6
// baseline (speedup 1.0000x reference)
#include <cuda_runtime.h>

// Problem-size caps (fixed by setup_inputs: N=100000, E=3200000)
#define MAXN 100000
#define MAXE 3200000
#define SCAN_B 512
#define MAXNB 256   // ceil(MAXN/SCAN_B)=196 <= 256

// ---------------- scratch (device globals; no allocation allowed) -----------
__device__ float g_score[MAXN];
__device__ float g_v[MAXN * 16];
__device__ __align__(16) float g_hA[MAXN * 32];    // pre-aggregation h of current layer
__device__ __align__(16) float g_hB[MAXN * 32];    // aggregated output of current layer
__device__ __align__(16) float g_x4[MAXN * 8];     // final GAT output
__device__ float g_es[MAXN * 8];
__device__ float g_ed[MAXN * 8];
__device__ int   g_cnt[2 * MAXN];             // [0..MAXN)=dst counts, [MAXN..)=src counts
__device__ int   g_rp[2 * (MAXN + 1)];        // rowptrs (dst then src)
__device__ int   g_cur[2 * MAXN];             // scatter cursors
__device__ int   g_col_dst[MAXE + MAXN];      // CSR(dst): src indices (incl self loops)
__device__ int   g_col_src[MAXE];             // CSR(src): dst indices (no self loops)
__device__ int   g_bsum[2 * MAXNB];
__device__ unsigned g_maxbits;
__device__ float g_sum;

// monotone float<->uint encoding for atomicMax on floats
__device__ __forceinline__ unsigned fenc(float f) {
    unsigned u = __float_as_uint(f);
    return (u & 0x80000000u) ? ~u : (u | 0x80000000u);
}
__device__ __forceinline__ float fdec(unsigned u) {
    u = (u & 0x80000000u) ? (u & 0x7FFFFFFFu) : ~u;
    return __uint_as_float(u);
}

// ---------------- init ----------------
__global__ void k_init(int n) {
    int i = blockIdx.x * blockDim.x + threadIdx.x;
    if (i < n) {
        g_cnt[i] = 1;          // dst count starts at 1: self loop
        g_cnt[MAXN + i] = 0;   // src count (final readout, no self loops)
    }
    if (i == 0) { g_maxbits = 0u; g_sum = 0.f; }
}

// ---------------- front: q,k,v, score ----------------
__global__ void k_front(const float* __restrict__ x1, const float* __restrict__ x2,
                        const float* __restrict__ Wq, const float* __restrict__ bq,
                        const float* __restrict__ Wk, const float* __restrict__ bk,
                        const float* __restrict__ Wv, const float* __restrict__ bv,
                        int n) {
    __shared__ float sWq[128], sWk[160], sWv[288], sbq[16], sbk[16], sbv[16];
    int t = threadIdx.x;
    for (int j = t; j < 128; j += blockDim.x) sWq[j] = Wq[j];
    for (int j = t; j < 160; j += blockDim.x) sWk[j] = Wk[j];
    for (int j = t; j < 288; j += blockDim.x) sWv[j] = Wv[j];
    if (t < 16) { sbq[t] = bq[t]; sbk[t] = bk[t]; sbv[t] = bv[t]; }
    __syncthreads();
    int i = blockIdx.x * blockDim.x + t;
    if (i >= n) return;
    float a[18];
#pragma unroll
    for (int j = 0; j < 8; j++)  a[j] = x1[i * 8 + j];
#pragma unroll
    for (int j = 0; j < 10; j++) a[8 + j] = x2[i * 10 + j];
    float sc = 0.f;
#pragma unroll
    for (int o = 0; o < 16; o++) {
        float q = sbq[o], k = sbk[o], v = sbv[o];
#pragma unroll
        for (int j = 0; j < 8; j++)  q += a[j] * sWq[j * 16 + o];
#pragma unroll
        for (int j = 0; j < 10; j++) k += a[8 + j] * sWk[j * 16 + o];
#pragma unroll
        for (int j = 0; j < 18; j++) v += a[j] * sWv[j * 16 + o];
        sc += q * k;
        g_v[i * 16 + o] = v;
    }
    g_score[i] = sc;
}

// ---------------- global softmax reductions ----------------
__global__ void k_max(int n) {
    __shared__ float sh[256];
    float m = -3.0e38f;
    for (int i = blockIdx.x * blockDim.x + threadIdx.x; i < n; i += gridDim.x * blockDim.x)
        m = fmaxf(m, g_score[i]);
    sh[threadIdx.x] = m; __syncthreads();
    for (int s = 128; s > 0; s >>= 1) {
        if (threadIdx.x < s) sh[threadIdx.x] = fmaxf(sh[threadIdx.x], sh[threadIdx.x + s]);
        __syncthreads();
    }
    if (threadIdx.x == 0) atomicMax(&g_maxbits, fenc(sh[0]));
}

__global__ void k_sum(int n) {
    __shared__ float sh[256];
    float m = fdec(g_maxbits);
    float s = 0.f;
    for (int i = blockIdx.x * blockDim.x + threadIdx.x; i < n; i += gridDim.x * blockDim.x)
        s += __expf(g_score[i] - m);
    sh[threadIdx.x] = s; __syncthreads();
    for (int st = 128; st > 0; st >>= 1) {
        if (threadIdx.x < st) sh[threadIdx.x] += sh[threadIdx.x + st];
        __syncthreads();
    }
    if (threadIdx.x == 0) atomicAdd(&g_sum, sh[0]);
}

// ---------------- CSR build ----------------
__global__ void k_count(const int* __restrict__ ei, int E) {
    int e = blockIdx.x * blockDim.x + threadIdx.x;
    if (e < E) {
        atomicAdd(&g_cnt[ei[E + e]], 1);        // dst
        atomicAdd(&g_cnt[MAXN + ei[e]], 1);     // src
    }
}

__global__ void k_scanA(int n) {
    __shared__ int sh[SCAN_B];
    int w = blockIdx.y;
    int t = threadIdx.x;
    int i = blockIdx.x * SCAN_B + t;
    int v = (i < n) ? g_cnt[w * MAXN + i] : 0;
    sh[t] = v;
    __syncthreads();
    for (int off = 1; off < SCAN_B; off <<= 1) {
        int add = (t >= off) ? sh[t - off] : 0;
        __syncthreads();
        sh[t] += add;
        __syncthreads();
    }
    if (i < n) g_rp[w * (MAXN + 1) + i] = sh[t] - v;   // exclusive within block
    if (t == SCAN_B - 1) g_bsum[w * MAXNB + blockIdx.x] = sh[t];
}

__global__ void k_scanB(int nb) {
    __shared__ int sh[MAXNB];
    int t = threadIdx.x;
    for (int w = 0; w < 2; w++) {
        int v = (t < nb) ? g_bsum[w * MAXNB + t] : 0;
        sh[t] = v;
        __syncthreads();
        for (int off = 1; off < MAXNB; off <<= 1) {
            int add = (t >= off) ? sh[t - off] : 0;
            __syncthreads();
            sh[t] += add;
            __syncthreads();
        }
        if (t < nb) g_bsum[w * MAXNB + t] = sh[t] - v;  // exclusive block offsets
        __syncthreads();
    }
}

__global__ void k_scanC(int n) {
    int i = blockIdx.x * blockDim.x + threadIdx.x;
    if (i >= n) return;
#pragma unroll
    for (int w = 0; w < 2; w++) {
        int off = g_bsum[w * MAXNB + i / SCAN_B];
        int r = g_rp[w * (MAXN + 1) + i] + off;
        g_rp[w * (MAXN + 1) + i] = r;
        g_cur[w * MAXN + i] = r;
        if (i == n - 1) g_rp[w * (MAXN + 1) + n] = r + g_cnt[w * MAXN + i];
    }
}

__global__ void k_scatter(const int* __restrict__ ei, int E, int n) {
    int e = blockIdx.x * blockDim.x + threadIdx.x;
    if (e < E) {
        int s = ei[e], d = ei[E + e];
        int p = atomicAdd(&g_cur[d], 1);
        g_col_dst[p] = s;
        int p2 = atomicAdd(&g_cur[MAXN + s], 1);
        g_col_src[p2] = d;
    }
    if (e < n) {  // self loop into dst-CSR
        int p = atomicAdd(&g_cur[e], 1);
        g_col_dst[p] = e;
    }
}

// ---------------- GAT node kernels (h = x@W, es, ed) ----------------
__global__ void k_node1(const float* __restrict__ W, const float* __restrict__ as_,
                        const float* __restrict__ ad_, int n) {
    __shared__ float sW[16 * 32], sas[32], sad[32];
    int t = threadIdx.x;
    for (int j = t; j < 512; j += blockDim.x) sW[j] = W[j];
    if (t < 32) { sas[t] = as_[t]; sad[t] = ad_[t]; }
    __syncthreads();
    int i = blockIdx.x * blockDim.x + t;
    if (i >= n) return;
    float m = fdec(g_maxbits);
    float coef = __expf(g_score[i] - m) * (1.0f / g_sum);  // global softmax weight
    float in[16];
#pragma unroll
    for (int j = 0; j < 16; j++) in[j] = coef * g_v[i * 16 + j];
    float h[32];
#pragma unroll
    for (int o = 0; o < 32; o++) {
        float acc = 0.f;
#pragma unroll
        for (int j = 0; j < 16; j++) acc += in[j] * sW[j * 32 + o];
        h[o] = acc;
        g_hA[i * 32 + o] = acc;
    }
#pragma unroll
    for (int hd = 0; hd < 8; hd++) {
        float es = 0.f, ed = 0.f;
#pragma unroll
        for (int c = 0; c < 4; c++) {
            es += h[hd * 4 + c] * sas[hd * 4 + c];
            ed += h[hd * 4 + c] * sad[hd * 4 + c];
        }
        g_es[i * 8 + hd] = es;
        g_ed[i * 8 + hd] = ed;
    }
}

template <int IN, int OUT, int H>
__global__ void k_nodeG(const float* __restrict__ W, const float* __restrict__ as_,
                        const float* __restrict__ ad_, int n) {
    constexpr int C = OUT / H;
    __shared__ float sW[IN * OUT], sas[OUT], sad[OUT];
    int t = threadIdx.x;
    for (int j = t; j < IN * OUT; j += blockDim.x) sW[j] = W[j];
    if (t < OUT) { sas[t] = as_[t]; sad[t] = ad_[t]; }
    __syncthreads();
    int i = blockIdx.x * blockDim.x + t;
    if (i >= n) return;
    float a[IN];
#pragma unroll
    for (int j = 0; j < IN; j++) a[j] = g_hB[i * IN + j];
    float h[OUT];
#pragma unroll
    for (int o = 0; o < OUT; o++) {
        float acc = 0.f;
#pragma unroll
        for (int j = 0; j < IN; j++) acc += a[j] * sW[j * OUT + o];
        h[o] = acc;
        g_hA[i * OUT + o] = acc;
    }
#pragma unroll
    for (int hd = 0; hd < H; hd++) {
        float es = 0.f, ed = 0.f;
#pragma unroll
        for (int c = 0; c < C; c++) {
            es += h[hd * C + c] * sas[hd * C + c];
            ed += h[hd * C + c] * sad[hd * C + c];
        }
        g_es[i * H + hd] = es;
        g_ed[i * H + hd] = ed;
    }
}

// ---------------- GAT edge kernel: warp-per-dst fused softmax+aggregation ----
// One WARP per destination node. Lanes = (32/H) edge-subgroups x H heads:
// lane = sub*H + hd. Each warp iteration processes 32/H edges of the SAME dst
// (iterations = ceil(deg / (32/H)); imbalance <= 1 edge — no max-of-k waste).
// Per-(edge,head): 1 col broadcast LDG, 1 es LDG, 1 float4 h LDG, 1 exp, 5 FMA.
// Final cross-subgroup shuffle reduction (log2(32/H) rounds), lanes<H write.
// Shift-free exp is exact for alpha (softmax shift invariance; logits tiny).
template <int H, bool TO_X4>
__global__ void k_edgeW(const float* __restrict__ bias, int n) {
    constexpr int SUB = 32 / H;   // edges in flight per warp iteration
    int gw = (blockIdx.x * blockDim.x + threadIdx.x) >> 5;
    int lane = threadIdx.x & 31;
    if (gw >= n) return;
    int d = gw;
    int sub = lane / H;
    int hd = lane % H;
    float edv = g_ed[d * H + hd];
    int p0 = g_rp[d], p1 = g_rp[d + 1];
    float z = 0.f;
    float4 S = make_float4(0.f, 0.f, 0.f, 0.f);
    const float4* __restrict__ hA4 = (const float4*)g_hA;
    for (int p = p0 + sub; p < p1; p += SUB) {
        int c = __ldg(&g_col_dst[p]);
        float e = __ldg(&g_es[c * H + hd]) + edv;
        e = (e > 0.f) ? e : 0.2f * e;
        float ee = __expf(e);
        float4 hv = __ldg(&hA4[c * H + hd]);
        z += ee;
        S.x += ee * hv.x;
        S.y += ee * hv.y;
        S.z += ee * hv.z;
        S.w += ee * hv.w;
    }
    // reduce across subgroups (same hd, different sub)
#pragma unroll
    for (int off = H; off < 32; off <<= 1) {
        z   += __shfl_xor_sync(0xffffffffu, z,   off);
        S.x += __shfl_xor_sync(0xffffffffu, S.x, off);
        S.y += __shfl_xor_sync(0xffffffffu, S.y, off);
        S.z += __shfl_xor_sync(0xffffffffu, S.z, off);
        S.w += __shfl_xor_sync(0xffffffffu, S.w, off);
    }
    if (lane < H) {
        float inv = 1.0f / z;
        float4 bv = __ldg(&((const float4*)bias)[hd]);
        float4 o;
        o.x = S.x * inv + bv.x;
        o.y = S.y * inv + bv.y;
        o.z = S.z * inv + bv.z;
        o.w = S.w * inv + bv.w;
        float4* dst = TO_X4 ? (float4*)g_x4 : (float4*)g_hB;
        dst[d * H + hd] = o;
    }
}

// ---------------- final readout (warp-per-node) ----------------
// Lanes = 16 edge-subgroups x 2 halves (float4 each). R3 = mean over
// out-neighbors of x4; out[i] = sum_ch R3*(x4 + Wl2). Whole-warp scalar
// reduction at the end.
__global__ void k_finalW(const float* __restrict__ Wl2, float* __restrict__ out, int n) {
    int gw = (blockIdx.x * blockDim.x + threadIdx.x) >> 5;
    int lane = threadIdx.x & 31;
    if (gw >= n) return;
    int i = gw;
    int sub = lane >> 1;      // 0..15
    int half = lane & 1;
    int p0 = g_rp[(MAXN + 1) + i], p1 = g_rp[(MAXN + 1) + i + 1];
    const float4* __restrict__ x44 = (const float4*)g_x4;
    float4 acc = make_float4(0.f, 0.f, 0.f, 0.f);
    for (int p = p0 + sub; p < p1; p += 16) {
        int c = __ldg(&g_col_src[p]);
        float4 v = __ldg(&x44[c * 2 + half]);
        acc.x += v.x; acc.y += v.y; acc.z += v.z; acc.w += v.w;
    }
    float4 xv = __ldg(&x44[i * 2 + half]);
    float4 wv = __ldg(&((const float4*)Wl2)[half]);
    float t = acc.x * (xv.x + wv.x)
            + acc.y * (xv.y + wv.y)
            + acc.z * (xv.z + wv.z)
            + acc.w * (xv.w + wv.w);
#pragma unroll
    for (int off = 16; off > 0; off >>= 1)
        t += __shfl_xor_sync(0xffffffffu, t, off);
    if (lane == 0) {
        int deg = p1 - p0;
        float inv = (deg > 0) ? 1.0f / (float)deg : 0.f;
        out[i] = t * inv;
    }
}

// ---------------- launch ----------------
extern "C" void kernel_launch(void* const* d_in, const int* in_sizes, int n_in,
                              void* d_out, int out_size) {
    const float* x1  = (const float*)d_in[0];
    const float* x2  = (const float*)d_in[1];
    const int*   ei  = (const int*)  d_in[2];
    // d_in[3] = num_nodes (unused; derived from sizes)
    const float* Wq  = (const float*)d_in[4];
    const float* bq  = (const float*)d_in[5];
    const float* Wk  = (const float*)d_in[6];
    const float* bk  = (const float*)d_in[7];
    const float* Wv  = (const float*)d_in[8];
    const float* bv  = (const float*)d_in[9];
    const float* W1  = (const float*)d_in[10];
    const float* a1s = (const float*)d_in[11];
    const float* a1d = (const float*)d_in[12];
    const float* b1  = (const float*)d_in[13];
    const float* W2  = (const float*)d_in[14];
    const float* a2s = (const float*)d_in[15];
    const float* a2d = (const float*)d_in[16];
    const float* b2  = (const float*)d_in[17];
    const float* W3  = (const float*)d_in[18];
    const float* a3s = (const float*)d_in[19];
    const float* a3d = (const float*)d_in[20];
    const float* b3  = (const float*)d_in[21];
    const float* Wl2 = (const float*)d_in[22];

    int n = in_sizes[0] / 8;
    int E = in_sizes[2] / 2;
    const int B = 256;
    int gN = (n + B - 1) / B;
    int gE = (E + B - 1) / B;
    int nb = (n + SCAN_B - 1) / SCAN_B;
    int gW = (n * 32 + B - 1) / B;   // warp-per-node grids

    k_init<<<gN, B>>>(n);
    k_front<<<gN, B>>>(x1, x2, Wq, bq, Wk, bk, Wv, bv, n);
    k_count<<<gE, B>>>(ei, E);
    {
        dim3 g(nb, 2);
        k_scanA<<<g, SCAN_B>>>(n);
    }
    k_scanB<<<1, MAXNB>>>(nb);
    k_scanC<<<gN, B>>>(n);
    k_scatter<<<gE, B>>>(ei, E, n);
    k_max<<<256, 256>>>(n);
    k_sum<<<256, 256>>>(n);

    // GAT layer 1: 16 -> 32 (H=8)
    k_node1<<<gN, B>>>(W1, a1s, a1d, n);
    k_edgeW<8, false><<<gW, B>>>(b1, n);

    // GAT layer 2: 32 -> 16 (H=4)
    k_nodeG<32, 16, 4><<<gN, B>>>(W2, a2s, a2d, n);
    k_edgeW<4, false><<<gW, B>>>(b2, n);

    // GAT layer 3: 16 -> 8 (H=2)
    k_nodeG<16, 8, 2><<<gN, B>>>(W3, a3s, a3d, n);
    k_edgeW<2, true><<<gW, B>>>(b3, n);

    k_finalW<<<gW, B>>>(Wl2, (float*)d_out, n);
}

// round 7
// speedup vs baseline: 1.4629x; 1.4629x over previous
#include <cuda_runtime.h>

// Problem-size caps (fixed by setup_inputs: N=100000, E=3200000)
#define MAXN 100000
#define MAXE 3200000
#define SCAN_B 512
#define MAXNB 256   // ceil(MAXN/SCAN_B)=196 <= 256

// ---------------- scratch (device globals; no allocation allowed) -----------
__device__ float g_score[MAXN];
__device__ float g_v[MAXN * 16];
__device__ __align__(16) float g_hA[MAXN * 32];    // pre-aggregation h of current layer
__device__ __align__(16) float g_hB[MAXN * 32];    // aggregated output of current layer
__device__ __align__(16) float g_x4[MAXN * 8];     // final GAT output
__device__ float g_es[MAXN * 8];
__device__ float g_ed[MAXN * 8];
__device__ int   g_cnt[2 * MAXN];             // [0..MAXN)=dst counts, [MAXN..)=src counts
__device__ int   g_rp[2 * (MAXN + 1)];        // rowptrs (dst then src)
__device__ int   g_cur[2 * MAXN];             // scatter cursors
__device__ int   g_col_dst[MAXE + MAXN];      // CSR(dst): src indices (incl self loops)
__device__ int   g_col_src[MAXE];             // CSR(src): dst indices (no self loops)
__device__ int   g_bsum[2 * MAXNB];
__device__ unsigned g_maxbits;
__device__ float g_sum;

// monotone float<->uint encoding for atomicMax on floats
__device__ __forceinline__ unsigned fenc(float f) {
    unsigned u = __float_as_uint(f);
    return (u & 0x80000000u) ? ~u : (u | 0x80000000u);
}
__device__ __forceinline__ float fdec(unsigned u) {
    u = (u & 0x80000000u) ? (u & 0x7FFFFFFFu) : ~u;
    return __uint_as_float(u);
}

// ---------------- init ----------------
__global__ void k_init(int n) {
    int i = blockIdx.x * blockDim.x + threadIdx.x;
    if (i < n) {
        g_cnt[i] = 1;          // dst count starts at 1: self loop
        g_cnt[MAXN + i] = 0;   // src count (final readout, no self loops)
    }
    if (i == 0) { g_maxbits = 0u; g_sum = 0.f; }
}

// ---------------- front: q,k,v, score ----------------
__global__ void k_front(const float* __restrict__ x1, const float* __restrict__ x2,
                        const float* __restrict__ Wq, const float* __restrict__ bq,
                        const float* __restrict__ Wk, const float* __restrict__ bk,
                        const float* __restrict__ Wv, const float* __restrict__ bv,
                        int n) {
    __shared__ float sWq[128], sWk[160], sWv[288], sbq[16], sbk[16], sbv[16];
    int t = threadIdx.x;
    for (int j = t; j < 128; j += blockDim.x) sWq[j] = Wq[j];
    for (int j = t; j < 160; j += blockDim.x) sWk[j] = Wk[j];
    for (int j = t; j < 288; j += blockDim.x) sWv[j] = Wv[j];
    if (t < 16) { sbq[t] = bq[t]; sbk[t] = bk[t]; sbv[t] = bv[t]; }
    __syncthreads();
    int i = blockIdx.x * blockDim.x + t;
    if (i >= n) return;
    float a[18];
#pragma unroll
    for (int j = 0; j < 8; j++)  a[j] = x1[i * 8 + j];
#pragma unroll
    for (int j = 0; j < 10; j++) a[8 + j] = x2[i * 10 + j];
    float sc = 0.f;
#pragma unroll
    for (int o = 0; o < 16; o++) {
        float q = sbq[o], k = sbk[o], v = sbv[o];
#pragma unroll
        for (int j = 0; j < 8; j++)  q += a[j] * sWq[j * 16 + o];
#pragma unroll
        for (int j = 0; j < 10; j++) k += a[8 + j] * sWk[j * 16 + o];
#pragma unroll
        for (int j = 0; j < 18; j++) v += a[j] * sWv[j * 16 + o];
        sc += q * k;
        g_v[i * 16 + o] = v;
    }
    g_score[i] = sc;
}

// ---------------- global softmax reductions ----------------
__global__ void k_max(int n) {
    __shared__ float sh[256];
    float m = -3.0e38f;
    for (int i = blockIdx.x * blockDim.x + threadIdx.x; i < n; i += gridDim.x * blockDim.x)
        m = fmaxf(m, g_score[i]);
    sh[threadIdx.x] = m; __syncthreads();
    for (int s = 128; s > 0; s >>= 1) {
        if (threadIdx.x < s) sh[threadIdx.x] = fmaxf(sh[threadIdx.x], sh[threadIdx.x + s]);
        __syncthreads();
    }
    if (threadIdx.x == 0) atomicMax(&g_maxbits, fenc(sh[0]));
}

__global__ void k_sum(int n) {
    __shared__ float sh[256];
    float m = fdec(g_maxbits);
    float s = 0.f;
    for (int i = blockIdx.x * blockDim.x + threadIdx.x; i < n; i += gridDim.x * blockDim.x)
        s += __expf(g_score[i] - m);
    sh[threadIdx.x] = s; __syncthreads();
    for (int st = 128; st > 0; st >>= 1) {
        if (threadIdx.x < st) sh[threadIdx.x] += sh[threadIdx.x + st];
        __syncthreads();
    }
    if (threadIdx.x == 0) atomicAdd(&g_sum, sh[0]);
}

// ---------------- CSR build ----------------
__global__ void k_count(const int* __restrict__ ei, int E) {
    int e = blockIdx.x * blockDim.x + threadIdx.x;
    if (e < E) {
        atomicAdd(&g_cnt[ei[E + e]], 1);        // dst
        atomicAdd(&g_cnt[MAXN + ei[e]], 1);     // src
    }
}

__global__ void k_scanA(int n) {
    __shared__ int sh[SCAN_B];
    int w = blockIdx.y;
    int t = threadIdx.x;
    int i = blockIdx.x * SCAN_B + t;
    int v = (i < n) ? g_cnt[w * MAXN + i] : 0;
    sh[t] = v;
    __syncthreads();
    for (int off = 1; off < SCAN_B; off <<= 1) {
        int add = (t >= off) ? sh[t - off] : 0;
        __syncthreads();
        sh[t] += add;
        __syncthreads();
    }
    if (i < n) g_rp[w * (MAXN + 1) + i] = sh[t] - v;   // exclusive within block
    if (t == SCAN_B - 1) g_bsum[w * MAXNB + blockIdx.x] = sh[t];
}

__global__ void k_scanB(int nb) {
    __shared__ int sh[MAXNB];
    int t = threadIdx.x;
    for (int w = 0; w < 2; w++) {
        int v = (t < nb) ? g_bsum[w * MAXNB + t] : 0;
        sh[t] = v;
        __syncthreads();
        for (int off = 1; off < MAXNB; off <<= 1) {
            int add = (t >= off) ? sh[t - off] : 0;
            __syncthreads();
            sh[t] += add;
            __syncthreads();
        }
        if (t < nb) g_bsum[w * MAXNB + t] = sh[t] - v;  // exclusive block offsets
        __syncthreads();
    }
}

__global__ void k_scanC(int n) {
    int i = blockIdx.x * blockDim.x + threadIdx.x;
    if (i >= n) return;
#pragma unroll
    for (int w = 0; w < 2; w++) {
        int off = g_bsum[w * MAXNB + i / SCAN_B];
        int r = g_rp[w * (MAXN + 1) + i] + off;
        g_rp[w * (MAXN + 1) + i] = r;
        g_cur[w * MAXN + i] = r;
        if (i == n - 1) g_rp[w * (MAXN + 1) + n] = r + g_cnt[w * MAXN + i];
    }
}

__global__ void k_scatter(const int* __restrict__ ei, int E, int n) {
    int e = blockIdx.x * blockDim.x + threadIdx.x;
    if (e < E) {
        int s = ei[e], d = ei[E + e];
        int p = atomicAdd(&g_cur[d], 1);
        g_col_dst[p] = s;
        int p2 = atomicAdd(&g_cur[MAXN + s], 1);
        g_col_src[p2] = d;
    }
    if (e < n) {  // self loop into dst-CSR
        int p = atomicAdd(&g_cur[e], 1);
        g_col_dst[p] = e;
    }
}

// ---------------- GAT node kernels (h = x@W, es, ed) ----------------
__global__ void k_node1(const float* __restrict__ W, const float* __restrict__ as_,
                        const float* __restrict__ ad_, int n) {
    __shared__ float sW[16 * 32], sas[32], sad[32];
    int t = threadIdx.x;
    for (int j = t; j < 512; j += blockDim.x) sW[j] = W[j];
    if (t < 32) { sas[t] = as_[t]; sad[t] = ad_[t]; }
    __syncthreads();
    int i = blockIdx.x * blockDim.x + t;
    if (i >= n) return;
    float m = fdec(g_maxbits);
    float coef = __expf(g_score[i] - m) * (1.0f / g_sum);  // global softmax weight
    float in[16];
#pragma unroll
    for (int j = 0; j < 16; j++) in[j] = coef * g_v[i * 16 + j];
    float h[32];
#pragma unroll
    for (int o = 0; o < 32; o++) {
        float acc = 0.f;
#pragma unroll
        for (int j = 0; j < 16; j++) acc += in[j] * sW[j * 32 + o];
        h[o] = acc;
        g_hA[i * 32 + o] = acc;
    }
#pragma unroll
    for (int hd = 0; hd < 8; hd++) {
        float es = 0.f, ed = 0.f;
#pragma unroll
        for (int c = 0; c < 4; c++) {
            es += h[hd * 4 + c] * sas[hd * 4 + c];
            ed += h[hd * 4 + c] * sad[hd * 4 + c];
        }
        g_es[i * 8 + hd] = es;
        g_ed[i * 8 + hd] = ed;
    }
}

template <int IN, int OUT, int H>
__global__ void k_nodeG(const float* __restrict__ W, const float* __restrict__ as_,
                        const float* __restrict__ ad_, int n) {
    constexpr int C = OUT / H;
    __shared__ float sW[IN * OUT], sas[OUT], sad[OUT];
    int t = threadIdx.x;
    for (int j = t; j < IN * OUT; j += blockDim.x) sW[j] = W[j];
    if (t < OUT) { sas[t] = as_[t]; sad[t] = ad_[t]; }
    __syncthreads();
    int i = blockIdx.x * blockDim.x + t;
    if (i >= n) return;
    float a[IN];
#pragma unroll
    for (int j = 0; j < IN; j++) a[j] = g_hB[i * IN + j];
    float h[OUT];
#pragma unroll
    for (int o = 0; o < OUT; o++) {
        float acc = 0.f;
#pragma unroll
        for (int j = 0; j < IN; j++) acc += a[j] * sW[j * OUT + o];
        h[o] = acc;
        g_hA[i * OUT + o] = acc;
    }
#pragma unroll
    for (int hd = 0; hd < H; hd++) {
        float es = 0.f, ed = 0.f;
#pragma unroll
        for (int c = 0; c < C; c++) {
            es += h[hd * C + c] * sas[hd * C + c];
            ed += h[hd * C + c] * sad[hd * C + c];
        }
        g_es[i * H + hd] = es;
        g_ed[i * H + hd] = ed;
    }
}

// ---------------- GAT edge kernel: fused softmax + aggregation ----------------
// One lane per (dst, head); lane owns the head's C=4 channels via float4 loads.
// Software-pipelined: col[p+1] and its es/h loads are issued before consuming
// the current edge's values, collapsing the per-iteration dependent chain from
// (col -> es/h) ~480cyc to ~240cyc. dst-CSR rows are never empty (self-loop),
// so the prologue load is safe. Shift-free exp is exact for alpha (softmax
// shift invariance; logits are tiny). Zero atomics; single edge pass per layer.
template <int H, bool TO_X4>
__global__ void k_edge(const float* __restrict__ bias, int n) {
    int tid = blockIdx.x * blockDim.x + threadIdx.x;
    int d = tid / H;
    int hd = tid % H;
    if (d >= n) return;
    float edv = g_ed[d * H + hd];
    int p0 = g_rp[d], p1 = g_rp[d + 1];
    float z = 0.f;
    float4 S = make_float4(0.f, 0.f, 0.f, 0.f);
    const float4* __restrict__ hA4 = (const float4*)g_hA;
    // prologue: deg >= 1 always (self-loop)
    int c = __ldg(&g_col_dst[p0]);
    float ev = __ldg(&g_es[c * H + hd]);
    float4 hv = __ldg(&hA4[c * H + hd]);
    for (int p = p0; p < p1; p++) {
        int pn = (p + 1 < p1) ? p + 1 : p;       // clamp: last iter reloads same
        int c2 = __ldg(&g_col_dst[pn]);
        float ev2 = __ldg(&g_es[c2 * H + hd]);
        float4 hv2 = __ldg(&hA4[c2 * H + hd]);
        float e = ev + edv;
        e = (e > 0.f) ? e : 0.2f * e;
        float ee = __expf(e);
        z += ee;
        S.x += ee * hv.x;
        S.y += ee * hv.y;
        S.z += ee * hv.z;
        S.w += ee * hv.w;
        ev = ev2; hv = hv2;
    }
    float inv = 1.0f / z;
    float4 bv = __ldg(&((const float4*)bias)[hd]);
    float4 o;
    o.x = S.x * inv + bv.x;
    o.y = S.y * inv + bv.y;
    o.z = S.z * inv + bv.z;
    o.w = S.w * inv + bv.w;
    float4* dst = TO_X4 ? (float4*)g_x4 : (float4*)g_hB;
    dst[d * H + hd] = o;
}

// ---------------- final readout ----------------
// 2 lanes per node, float4 each: R3 = mean over out-neighbors of x4;
// out[i] = sum_ch R3*(x4 + Wl2). Software-pipelined like k_edge; src-CSR rows
// CAN be empty, so the prologue is guarded.
__global__ void k_final(const float* __restrict__ Wl2, float* __restrict__ out, int n) {
    int tid = blockIdx.x * blockDim.x + threadIdx.x;
    int i = tid >> 1;
    int half = tid & 1;
    bool valid = (i < n);
    float t = 0.f;
    if (valid) {
        int p0 = g_rp[(MAXN + 1) + i], p1 = g_rp[(MAXN + 1) + i + 1];
        const float4* __restrict__ x44 = (const float4*)g_x4;
        float4 acc = make_float4(0.f, 0.f, 0.f, 0.f);
        if (p0 < p1) {
            int c = __ldg(&g_col_src[p0]);
            float4 v = __ldg(&x44[c * 2 + half]);
            for (int p = p0; p < p1; p++) {
                int pn = (p + 1 < p1) ? p + 1 : p;
                int c2 = __ldg(&g_col_src[pn]);
                float4 v2 = __ldg(&x44[c2 * 2 + half]);
                acc.x += v.x; acc.y += v.y; acc.z += v.z; acc.w += v.w;
                v = v2;
            }
        }
        int deg = p1 - p0;
        float inv = (deg > 0) ? 1.0f / (float)deg : 0.f;
        float4 xv = __ldg(&x44[i * 2 + half]);
        float4 wv = __ldg(&((const float4*)Wl2)[half]);
        t = acc.x * inv * (xv.x + wv.x)
          + acc.y * inv * (xv.y + wv.y)
          + acc.z * inv * (xv.z + wv.z)
          + acc.w * inv * (xv.w + wv.w);
    }
    t += __shfl_xor_sync(0xffffffffu, t, 1);
    if (valid && half == 0) out[i] = t;
}

// ---------------- launch ----------------
extern "C" void kernel_launch(void* const* d_in, const int* in_sizes, int n_in,
                              void* d_out, int out_size) {
    const float* x1  = (const float*)d_in[0];
    const float* x2  = (const float*)d_in[1];
    const int*   ei  = (const int*)  d_in[2];
    // d_in[3] = num_nodes (unused; derived from sizes)
    const float* Wq  = (const float*)d_in[4];
    const float* bq  = (const float*)d_in[5];
    const float* Wk  = (const float*)d_in[6];
    const float* bk  = (const float*)d_in[7];
    const float* Wv  = (const float*)d_in[8];
    const float* bv  = (const float*)d_in[9];
    const float* W1  = (const float*)d_in[10];
    const float* a1s = (const float*)d_in[11];
    const float* a1d = (const float*)d_in[12];
    const float* b1  = (const float*)d_in[13];
    const float* W2  = (const float*)d_in[14];
    const float* a2s = (const float*)d_in[15];
    const float* a2d = (const float*)d_in[16];
    const float* b2  = (const float*)d_in[17];
    const float* W3  = (const float*)d_in[18];
    const float* a3s = (const float*)d_in[19];
    const float* a3d = (const float*)d_in[20];
    const float* b3  = (const float*)d_in[21];
    const float* Wl2 = (const float*)d_in[22];

    int n = in_sizes[0] / 8;
    int E = in_sizes[2] / 2;
    const int B = 256;
    int gN = (n + B - 1) / B;
    int gE = (E + B - 1) / B;
    int nb = (n + SCAN_B - 1) / SCAN_B;

    k_init<<<gN, B>>>(n);
    k_front<<<gN, B>>>(x1, x2, Wq, bq, Wk, bk, Wv, bv, n);
    k_count<<<gE, B>>>(ei, E);
    {
        dim3 g(nb, 2);
        k_scanA<<<g, SCAN_B>>>(n);
    }
    k_scanB<<<1, MAXNB>>>(nb);
    k_scanC<<<gN, B>>>(n);
    k_scatter<<<gE, B>>>(ei, E, n);
    k_max<<<256, 256>>>(n);
    k_sum<<<256, 256>>>(n);

    // GAT layer 1: 16 -> 32 (H=8)
    k_node1<<<gN, B>>>(W1, a1s, a1d, n);
    k_edge<8, false><<<(n * 8 + B - 1) / B, B>>>(b1, n);

    // GAT layer 2: 32 -> 16 (H=4)
    k_nodeG<32, 16, 4><<<gN, B>>>(W2, a2s, a2d, n);
    k_edge<4, false><<<(n * 4 + B - 1) / B, B>>>(b2, n);

    // GAT layer 3: 16 -> 8 (H=2)
    k_nodeG<16, 8, 2><<<gN, B>>>(W3, a3s, a3d, n);
    k_edge<2, true><<<(n * 2 + B - 1) / B, B>>>(b3, n);

    k_final<<<(n * 2 + B - 1) / B, B>>>(Wl2, (float*)d_out, n);
}